// round 14
// baseline (speedup 1.0000x reference)
#include <cuda_runtime.h>
#include <cuda_fp16.h>
#include <math.h>
#include <stdint.h>

#define T 8
#define N 2048
#define F 128
#define C 64

// ---------------- device scratch ----------------
__device__ float g_es[T * N];
__device__ float g_ed[T * N];
__device__ float g_out[T * N * C];
__device__ __half g_hThi[T * C * N];   // h transposed fp16: [t][c][n]
__device__ __half g_Whi[C * F];        // W^T hi fp16: [c][k]
__device__ __half g_Wlo[C * F];        // W^T lo fp16

// ---------------- helpers ----------------
__device__ __forceinline__ uint32_t smem_u32(const void* p) {
    uint32_t a;
    asm("{ .reg .u64 t; cvta.to.shared.u64 t, %1; cvt.u32.u64 %0, t; }"
        : "=r"(a) : "l"(p));
    return a;
}
#define CP_ASYNC16(dst, src) \
    asm volatile("cp.async.cg.shared.global [%0], [%1], 16;" :: "r"(dst), "l"(src) : "memory")
#define CP_COMMIT() asm volatile("cp.async.commit_group;" ::: "memory")
#define CP_WAIT0() asm volatile("cp.async.wait_group 0;" ::: "memory")
#define CP_WAIT1() asm volatile("cp.async.wait_group 1;" ::: "memory")

__device__ __forceinline__ void ldsm4(uint32_t& r0, uint32_t& r1, uint32_t& r2,
                                      uint32_t& r3, uint32_t addr) {
    asm volatile("ldmatrix.sync.aligned.m8n8.x4.shared.b16 {%0,%1,%2,%3}, [%4];"
                 : "=r"(r0), "=r"(r1), "=r"(r2), "=r"(r3) : "r"(addr));
}
__device__ __forceinline__ void mma16816(float* d, const uint32_t* a, uint32_t b0,
                                         uint32_t b1) {
    asm volatile(
        "mma.sync.aligned.m16n8k16.row.col.f32.f16.f16.f32 "
        "{%0,%1,%2,%3}, {%4,%5,%6,%7}, {%8,%9}, {%0,%1,%2,%3};"
        : "+f"(d[0]), "+f"(d[1]), "+f"(d[2]), "+f"(d[3])
        : "r"(a[0]), "r"(a[1]), "r"(a[2]), "r"(a[3]), "r"(b0), "r"(b1));
}
__device__ __forceinline__ uint32_t pack_p(float p0, float p1) {
    __half2 h = __floats2half2_rn(p0, p1);
    return *(uint32_t*)&h;
}

// ---------------- f32x2 helpers ----------------
__device__ __forceinline__ unsigned long long pk2(float lo, float hi) {
    unsigned long long r;
    asm("mov.b64 %0, {%1, %2};" : "=l"(r) : "f"(lo), "f"(hi));
    return r;
}
__device__ __forceinline__ void upk2(unsigned long long v, float& lo, float& hi) {
    asm("mov.b64 {%0, %1}, %2;" : "=f"(lo), "=f"(hi) : "l"(v));
}
__device__ __forceinline__ void fma2(unsigned long long& d, unsigned long long a,
                                     unsigned long long b) {
    asm("fma.rn.f32x2 %0, %1, %2, %0;" : "+l"(d) : "l"(a), "l"(b));
}

// ============================================================
// Kernel W: one-time W -> transposed hi/lo fp16 (global)
// ============================================================
__global__ __launch_bounds__(256) void kW(const float* __restrict__ W) {
#pragma unroll
    for (int i = 0; i < 32; i++) {
        int e = threadIdx.x + i * 256;
        int k = e >> 6, c = e & 63;
        float v = W[e];
        __half h = __float2half_rn(v);
        g_Whi[c * F + k] = h;
        g_Wlo[c * F + k] = __float2half_rn(v - __half2float(h));
    }
}

// ============================================================
// Kernel A (HMMA): h = x @ W via split-fp16 (3 products).
// ============================================================
#define KA_WHI  0
#define KA_WLO  17408
#define KA_XHI  34816
#define KA_XLO  52224
#define KA_HHI  KA_XHI
#define KA_SMEM 69632

__global__ __launch_bounds__(128) void kA(const float* __restrict__ x,
                                          const float* __restrict__ asrc,
                                          const float* __restrict__ adst) {
    extern __shared__ __align__(16) char smA[];
    __half* xh = (__half*)(smA + KA_XHI);
    __half* xl = (__half*)(smA + KA_XLO);
    uint32_t smb = smem_u32(smA);

    int tid = threadIdx.x;
    int lane = tid & 31;
    int w = tid >> 5;
    int t = blockIdx.y;
    int n0 = blockIdx.x * 64;

#pragma unroll
    for (int r = 0; r < 8; r++) {
        int u = tid + r * 128;
        int c = u >> 4, seg = u & 15;
        uint32_t doff = (uint32_t)(c * 136 + seg * 8) * 2;
        CP_ASYNC16(smb + KA_WHI + doff, g_Whi + c * F + seg * 8);
        CP_ASYNC16(smb + KA_WLO + doff, g_Wlo + c * F + seg * 8);
    }
    CP_COMMIT();

    {
        int row = tid >> 1, half = tid & 1;
        const float4* xr4 =
            (const float4*)(x + ((size_t)t * N + n0 + row) * F + half * 64);
        __half* xhp = xh + row * 136 + half * 64;
        __half* xlp = xl + row * 136 + half * 64;
#pragma unroll
        for (int j = 0; j < 16; j++) {
            float4 v = xr4[j];
            __half2 h01 = __floats2half2_rn(v.x, v.y);
            __half2 h23 = __floats2half2_rn(v.z, v.w);
            float2 f01 = __half22float2(h01);
            float2 f23 = __half22float2(h23);
            __half2 l01 = __floats2half2_rn(v.x - f01.x, v.y - f01.y);
            __half2 l23 = __floats2half2_rn(v.z - f23.x, v.w - f23.y);
            *(uint32_t*)(xhp + j * 4) = *(uint32_t*)&h01;
            *(uint32_t*)(xhp + j * 4 + 2) = *(uint32_t*)&h23;
            *(uint32_t*)(xlp + j * 4) = *(uint32_t*)&l01;
            *(uint32_t*)(xlp + j * 4 + 2) = *(uint32_t*)&l23;
        }
    }
    CP_WAIT0();
    __syncthreads();

    float d[8][4];
#pragma unroll
    for (int nt = 0; nt < 8; nt++)
#pragma unroll
        for (int q = 0; q < 4; q++) d[nt][q] = 0.f;

    uint32_t xhi_b = smb + KA_XHI;
    uint32_t xlo_b = smb + KA_XLO;
    uint32_t whi_b = smb + KA_WHI;
    uint32_t wlo_b = smb + KA_WLO;
    int r0 = w * 16;
    uint32_t rowOffA = (lane & 7) + ((lane >> 3) & 1) * 8;
    uint32_t colOffA = (lane >> 4) * 8;
    uint32_t rowB = ((lane >> 4) << 3) + (lane & 7);
    uint32_t colB = ((lane >> 3) & 1) * 8;

#pragma unroll
    for (int ks = 0; ks < 8; ks++) {
        uint32_t kb = ks * 16;
        uint32_t aoff = ((r0 + rowOffA) * 136 + kb + colOffA) * 2;
        uint32_t ahi[4], alo[4];
        ldsm4(ahi[0], ahi[1], ahi[2], ahi[3], xhi_b + aoff);
        ldsm4(alo[0], alo[1], alo[2], alo[3], xlo_b + aoff);
#pragma unroll
        for (int cg = 0; cg < 4; cg++) {
            uint32_t boff = ((cg * 16 + rowB) * 136 + kb + colB) * 2;
            uint32_t h0, h1, h2, h3, l0, l1, l2, l3;
            ldsm4(h0, h1, h2, h3, whi_b + boff);
            ldsm4(l0, l1, l2, l3, wlo_b + boff);
            mma16816(d[cg * 2], ahi, h0, h1);
            mma16816(d[cg * 2], ahi, l0, l1);
            mma16816(d[cg * 2], alo, h0, h1);
            mma16816(d[cg * 2 + 1], ahi, h2, h3);
            mma16816(d[cg * 2 + 1], ahi, l2, l3);
            mma16816(d[cg * 2 + 1], alo, h2, h3);
        }
    }

    int r1 = r0 + (lane >> 2), r2 = r1 + 8;
    float es1 = 0.f, ed1 = 0.f, es2 = 0.f, ed2 = 0.f;
#pragma unroll
    for (int nt = 0; nt < 8; nt++) {
        int c = nt * 8 + 2 * (lane & 3);
        float a0 = asrc[c], a1 = asrc[c + 1];
        float b0 = adst[c], b1 = adst[c + 1];
        es1 += d[nt][0] * a0 + d[nt][1] * a1;
        ed1 += d[nt][0] * b0 + d[nt][1] * b1;
        es2 += d[nt][2] * a0 + d[nt][3] * a1;
        ed2 += d[nt][2] * b0 + d[nt][3] * b1;
    }
#pragma unroll
    for (int off = 1; off < 4; off <<= 1) {
        es1 += __shfl_xor_sync(0xffffffffu, es1, off);
        ed1 += __shfl_xor_sync(0xffffffffu, ed1, off);
        es2 += __shfl_xor_sync(0xffffffffu, es2, off);
        ed2 += __shfl_xor_sync(0xffffffffu, ed2, off);
    }
    if ((lane & 3) == 0) {
        g_es[t * N + n0 + r1] = es1;
        g_ed[t * N + n0 + r1] = ed1;
        g_es[t * N + n0 + r2] = es2;
        g_ed[t * N + n0 + r2] = ed2;
    }

    __syncthreads();
    __half* hh = (__half*)(smA + KA_HHI);
#pragma unroll
    for (int nt = 0; nt < 8; nt++) {
        int c = nt * 8 + 2 * (lane & 3);
        hh[c * 136 + r1] = __float2half_rn(d[nt][0]);
        hh[(c + 1) * 136 + r1] = __float2half_rn(d[nt][1]);
        hh[c * 136 + r2] = __float2half_rn(d[nt][2]);
        hh[(c + 1) * 136 + r2] = __float2half_rn(d[nt][3]);
    }
    __syncthreads();

    __half* dhi = g_hThi + (size_t)t * C * N;
#pragma unroll
    for (int i = 0; i < 4; i++) {
        int u = tid + i * 128;
        int c = u >> 3, seg = u & 7;
        *(uint4*)(dhi + (size_t)c * N + n0 + seg * 8) = *(uint4*)(hh + c * 136 + seg * 8);
    }
}

// ============================================================
// Kernel B: masked-softmax aggregation via fp16 HMMA.
// 512 threads, kt-split warp pairs. adj via direct registered LDG
// (each element read by exactly one thread), software-prefetched.
// H tiles via 3-deep cp.async, ONE sync/chunk.
// ============================================================
#define BB_OFF   0                     // 16384
#define HS_OFF   16384                 // 3 x 9216 = 27648
#define DCOMB_OFF 44032                // 32768
#define RED_OFF  76800                 // 2048
#define BIAS_OFF 78848                 // 256
#define KB_SMEM  79104

__global__ __launch_bounds__(512) void kB(const int* __restrict__ adj,
                                          const float* __restrict__ bias) {
    extern __shared__ __align__(16) char sm[];
    float2* BB = (float2*)(sm + BB_OFF);
    float* red = (float*)(sm + RED_OFF);
    float* bias_s = (float*)(sm + BIAS_OFF);
    uint32_t smb = smem_u32(sm);

    int tid = threadIdx.x;
    int wid = tid >> 5;
    int lane = tid & 31;
    int wl = wid & 7;
    int kh = wid >> 3;
    int t = blockIdx.y;
    int i0 = blockIdx.x * 128;

    const int* abase = adj + (size_t)t * N * N + i0;
    const __half* hhib = g_hThi + (size_t)t * C * N;

    int q = lane & 3;
    int c0j = 2 * q;
    int qd = lane >> 2;
    int il1 = wl * 16 + qd;
    int il2 = il1 + 8;
    int gi1 = i0 + il1, gi2 = i0 + il2;

    // adj base pointers for this thread's 16 slots (offsets const x N)
    const int* q1 = abase + il1 + (size_t)(kh * 32 + c0j) * N;
    const int* q2 = abase + il2 + (size_t)(kh * 32 + c0j) * N;

    int vreg[16];
#define LD_ADJ(v, q1, q2)                                     \
    do {                                                      \
        (v)[0] = (q1)[0];            (v)[1] = (q2)[0];        \
        (v)[2] = (q1)[(size_t)N];    (v)[3] = (q2)[(size_t)N];\
        (v)[4] = (q1)[(size_t)8*N];  (v)[5] = (q2)[(size_t)8*N];  \
        (v)[6] = (q1)[(size_t)9*N];  (v)[7] = (q2)[(size_t)9*N];  \
        (v)[8] = (q1)[(size_t)16*N]; (v)[9] = (q2)[(size_t)16*N]; \
        (v)[10] = (q1)[(size_t)17*N];(v)[11] = (q2)[(size_t)17*N];\
        (v)[12] = (q1)[(size_t)24*N];(v)[13] = (q2)[(size_t)24*N];\
        (v)[14] = (q1)[(size_t)25*N];(v)[15] = (q2)[(size_t)25*N];\
    } while (0)

    // ---- prologue: adj chunk 0 into registers; H chunks 0,1 via cp.async ----
    LD_ADJ(vreg, q1, q2);
#pragma unroll
    for (int b = 0; b < 2; b++) {
        int c = tid >> 3, o = tid & 7;
        uint32_t doff = (uint32_t)(c * 72 + o * 8) * 2;
        CP_ASYNC16(smb + HS_OFF + b * 9216 + doff, hhib + (size_t)c * N + b * 64 + o * 8);
        CP_COMMIT();
    }

    if (tid < 16) ((float4*)bias_s)[tid] = ((const float4*)bias)[tid];

    // ---- e_s staging + max + transform ----
    float lmax = -1e30f;
#pragma unroll
    for (int r = 0; r < 4; r++) {
        float v = g_es[t * N + tid + r * 512];
        BB[tid + r * 512].x = v;
        lmax = fmaxf(lmax, v);
    }
    red[tid] = lmax;
    __syncthreads();
    for (int s = 256; s > 0; s >>= 1) {
        if (tid < s) red[tid] = fmaxf(red[tid], red[tid + s]);
        __syncthreads();
    }
    float esmax = red[0];
#pragma unroll
    for (int r = 0; r < 4; r++) {
        int j = tid + r * 512;
        float v = BB[j].x;
        BB[j] = make_float2(__expf(v - esmax), __expf(0.2f * (v - esmax)));
    }

    // ---- per-row constants ----
    float ed1 = g_ed[t * N + gi1], ed2 = g_ed[t * N + gi2];
    float xm1 = ed1 + esmax, xm2 = ed2 + esmax;
    float M1 = fmaxf(xm1, 0.2f * xm1), M2 = fmaxf(xm2, 0.2f * xm2);
    float Ai1 = __expf(xm1 - M1), A2i1 = __expf(0.2f * xm1 - M1);
    float Ai2 = __expf(xm2 - M2), A2i2 = __expf(0.2f * xm2 - M2);

    float d[8][4];
#pragma unroll
    for (int nt = 0; nt < 8; nt++)
#pragma unroll
        for (int qq = 0; qq < 4; qq++) d[nt][qq] = 0.f;
    float sum1 = 0.f, sum2 = 0.f;

    uint32_t rowa = ((lane >> 4) << 3) + (lane & 7);
    uint32_t cola = ((lane >> 3) & 1) * 8;

    __syncthreads();   // BB ready

#pragma unroll 1
    for (int k = 0; k < 32; k++) {
        int j0 = k * 64;
        int bufk = k % 3;
        if (k < 31) { CP_WAIT1(); } else { CP_WAIT0(); }
        __syncthreads();   // H chunk k visible; prior ldsm done

        // ---- mask bits from vreg (chunk k), then prefetch chunk k+1 ----
        int sl1 = gi1 - j0, sl2 = gi2 - j0;
        unsigned mk = 0;
#pragma unroll
        for (int ktl = 0; ktl < 2; ktl++) {
#pragma unroll
            for (int dIdx = 0; dIdx < 4; dIdx++) {
                int dlt = (dIdx & 1) + (dIdx >> 1) * 8;
                int jj = (kh * 2 + ktl) * 16 + c0j + dlt;
                if (vreg[ktl * 8 + dIdx * 2] != 0 || jj == sl1)
                    mk |= 1u << (ktl * 8 + dIdx * 2);
                if (vreg[ktl * 8 + dIdx * 2 + 1] != 0 || jj == sl2)
                    mk |= 1u << (ktl * 8 + dIdx * 2 + 1);
            }
        }
        if (k + 1 < 32) {
            q1 += (size_t)64 * N;
            q2 += (size_t)64 * N;
            LD_ADJ(vreg, q1, q2);
        }

        // ---- refill H buf (k+2)%3 ----
        if (k + 2 < 32) {
            int bufn = (k + 2) % 3;
            int jn = j0 + 128;
            int c = tid >> 3, o = tid & 7;
            uint32_t doff = (uint32_t)(c * 72 + o * 8) * 2;
            CP_ASYNC16(smb + HS_OFF + (uint32_t)bufn * 9216 + doff,
                       hhib + (size_t)c * N + jn + o * 8);
            CP_COMMIT();
        }

        uint32_t hhi_u = smb + HS_OFF + (uint32_t)bufk * 9216;

#pragma unroll
        for (int ktl = 0; ktl < 2; ktl++) {
            int kt = kh * 2 + ktl;
            int jb = j0 + kt * 16 + c0j;
            float2 bA = BB[jb], bBv = BB[jb + 1], bCv = BB[jb + 8], bDv = BB[jb + 9];
            unsigned ml = mk >> (ktl * 8);

            float pc;
            float p1[4], p2[4];
            pc = fmaxf(Ai1 * bA.x, A2i1 * bA.y);  p1[0] = (ml & 1u) ? pc : 0.f;
            pc = fmaxf(Ai2 * bA.x, A2i2 * bA.y);  p2[0] = ((ml >> 1) & 1u) ? pc : 0.f;
            pc = fmaxf(Ai1 * bBv.x, A2i1 * bBv.y); p1[1] = ((ml >> 2) & 1u) ? pc : 0.f;
            pc = fmaxf(Ai2 * bBv.x, A2i2 * bBv.y); p2[1] = ((ml >> 3) & 1u) ? pc : 0.f;
            pc = fmaxf(Ai1 * bCv.x, A2i1 * bCv.y); p1[2] = ((ml >> 4) & 1u) ? pc : 0.f;
            pc = fmaxf(Ai2 * bCv.x, A2i2 * bCv.y); p2[2] = ((ml >> 5) & 1u) ? pc : 0.f;
            pc = fmaxf(Ai1 * bDv.x, A2i1 * bDv.y); p1[3] = ((ml >> 6) & 1u) ? pc : 0.f;
            pc = fmaxf(Ai2 * bDv.x, A2i2 * bDv.y); p2[3] = ((ml >> 7) & 1u) ? pc : 0.f;

            sum1 += (p1[0] + p1[1]) + (p1[2] + p1[3]);
            sum2 += (p2[0] + p2[1]) + (p2[2] + p2[3]);

            uint32_t ap[4];
            ap[0] = pack_p(p1[0], p1[1]);
            ap[1] = pack_p(p2[0], p2[1]);
            ap[2] = pack_p(p1[2], p1[3]);
            ap[3] = pack_p(p2[2], p2[3]);

            uint32_t lcol = (uint32_t)(kt * 16) + cola;
#pragma unroll
            for (int cg = 0; cg < 4; cg++) {
                uint32_t roff = ((uint32_t)(cg * 16) + rowa) * 144 + lcol * 2;
                uint32_t h0, h1, h2, h3;
                ldsm4(h0, h1, h2, h3, hhi_u + roff);
                mma16816(d[cg * 2], ap, h0, h1);
                mma16816(d[cg * 2 + 1], ap, h2, h3);
            }
        }
    }

    // ---- combine kt-halves ----
    sum1 += __shfl_xor_sync(0xffffffffu, sum1, 1);
    sum1 += __shfl_xor_sync(0xffffffffu, sum1, 2);
    sum2 += __shfl_xor_sync(0xffffffffu, sum2, 1);
    sum2 += __shfl_xor_sync(0xffffffffu, sum2, 2);

    __syncthreads();
    float* dc = (float*)(sm + DCOMB_OFF);
    float* sums_hi = (float*)(sm + RED_OFF);

    if (kh == 1) {
#pragma unroll
        for (int nt = 0; nt < 8; nt++)
            *(float4*)(dc + wl * 1024 + nt * 128 + lane * 4) =
                make_float4(d[nt][0], d[nt][1], d[nt][2], d[nt][3]);
        if ((lane & 3) == 0) {
            sums_hi[il1] = sum1;
            sums_hi[il2] = sum2;
        }
    }
    __syncthreads();

    if (kh == 0) {
        float st1 = sum1 + sums_hi[il1];
        float st2 = sum2 + sums_hi[il2];
        float s1 = 1.f / st1, s2 = 1.f / st2;

        float* o1 = g_out + ((size_t)t * N + gi1) * C;
        float* o2 = g_out + ((size_t)t * N + gi2) * C;
        int q2o = 2 * q;
#pragma unroll
        for (int nt = 0; nt < 8; nt++) {
            float4 pd = *(const float4*)(dc + wl * 1024 + nt * 128 + lane * 4);
            int c = nt * 8 + q2o;
            *(float2*)(o1 + c) = make_float2((d[nt][0] + pd.x) * s1 + bias_s[c],
                                             (d[nt][1] + pd.y) * s1 + bias_s[c + 1]);
            *(float2*)(o2 + c) = make_float2((d[nt][2] + pd.z) * s2 + bias_s[c],
                                             (d[nt][3] + pd.w) * s2 + bias_s[c + 1]);
        }
    }
}

// ============================================================
// Kernel C: inline cosine sims + temporal matvecs.
// 128 nodes/CTA, 4 nodes per thread.
// ============================================================
#define KC_W1 0
#define KC_W2 16384
#define KC_US 32768        // 128 x 66 float2 = 67584
#define KC_SMEM 100352

__global__ __launch_bounds__(256) void kC(const float* __restrict__ t1w,
                                          const float* __restrict__ t2w,
                                          float* __restrict__ out) {
    extern __shared__ __align__(16) char smC[];
    float* w1 = (float*)(smC + KC_W1);
    float* w2 = (float*)(smC + KC_W2);
    float2* us = (float2*)(smC + KC_US);

    int tid = threadIdx.x;
    int t = blockIdx.y;
    int n0 = blockIdx.x * 128;

#pragma unroll
    for (int r = 0; r < 4; r++) {
        ((float4*)w1)[tid + r * 256] = ((const float4*)t1w)[tid + r * 256];
        ((float4*)w2)[tid + r * 256] = ((const float4*)t2w)[tid + r * 256];
    }

    int nl = tid >> 3;
    int dg = (tid & 7) * 8;

    float curH[4][8];
    unsigned long long acc[4][4];

#pragma unroll
    for (int half = 0; half < 4; half++) {
        int node = nl + half * 32;
        size_t rowo = ((size_t)t * N + n0 + node) * C;
        float cur[8], prv[8], nxt[8];
#pragma unroll
        for (int qq = 0; qq < 2; qq++) {
            float4 v = *(const float4*)(g_out + rowo + dg + qq * 4);
            cur[qq * 4] = v.x; cur[qq * 4 + 1] = v.y;
            cur[qq * 4 + 2] = v.z; cur[qq * 4 + 3] = v.w;
        }
        if (t >= 1) {
#pragma unroll
            for (int qq = 0; qq < 2; qq++) {
                float4 v = *(const float4*)(g_out + rowo - (size_t)N * C + dg + qq * 4);
                prv[qq * 4] = v.x; prv[qq * 4 + 1] = v.y;
                prv[qq * 4 + 2] = v.z; prv[qq * 4 + 3] = v.w;
            }
        } else {
#pragma unroll
            for (int dd = 0; dd < 8; dd++) prv[dd] = 0.f;
        }
        if (t < T - 1) {
#pragma unroll
            for (int qq = 0; qq < 2; qq++) {
                float4 v = *(const float4*)(g_out + rowo + (size_t)N * C + dg + qq * 4);
                nxt[qq * 4] = v.x; nxt[qq * 4 + 1] = v.y;
                nxt[qq * 4 + 2] = v.z; nxt[qq * 4 + 3] = v.w;
            }
        } else {
#pragma unroll
            for (int dd = 0; dd < 8; dd++) nxt[dd] = 0.f;
        }

        float ab = 0.f, bc = 0.f, na = 0.f, nb = 0.f, nc = 0.f;
#pragma unroll
        for (int dd = 0; dd < 8; dd++) {
            ab = fmaf(prv[dd], cur[dd], ab);
            bc = fmaf(cur[dd], nxt[dd], bc);
            na = fmaf(prv[dd], prv[dd], na);
            nb = fmaf(cur[dd], cur[dd], nb);
            nc = fmaf(nxt[dd], nxt[dd], nc);
        }
#pragma unroll
        for (int off = 1; off < 8; off <<= 1) {
            ab += __shfl_xor_sync(0xffffffffu, ab, off);
            bc += __shfl_xor_sync(0xffffffffu, bc, off);
            na += __shfl_xor_sync(0xffffffffu, na, off);
            nb += __shfl_xor_sync(0xffffffffu, nb, off);
            nc += __shfl_xor_sync(0xffffffffu, nc, off);
        }
        float rb = fmaxf(sqrtf(nb), 1e-8f);
        float tem_prev = ab / (fmaxf(sqrtf(na), 1e-8f) * rb);
        float tem_next = bc / (rb * fmaxf(sqrtf(nc), 1e-8f));

        float2* urow = us + node * 66 + dg;
#pragma unroll
        for (int dd = 0; dd < 8; dd++)
            urow[dd] = make_float2(tem_next * nxt[dd], tem_prev * prv[dd]);

#pragma unroll
        for (int dd = 0; dd < 8; dd++) curH[half][dd] = cur[dd];
    }
    __syncthreads();

#pragma unroll
    for (int h = 0; h < 4; h++)
#pragma unroll
        for (int qq = 0; qq < 4; qq++)
            acc[h][qq] = pk2(curH[h][qq * 2], curH[h][qq * 2 + 1]);

    const float2* un0 = us + nl * 66;
#pragma unroll 2
    for (int c = 0; c < C; c++) {
        const ulonglong2* r1 = (const ulonglong2*)(w1 + c * C + dg);
        const ulonglong2* r2 = (const ulonglong2*)(w2 + c * C + dg);
        ulonglong2 wv1 = r1[0], wv1b = r1[1];
        ulonglong2 wv2 = r2[0], wv2b = r2[1];
#pragma unroll
        for (int h = 0; h < 4; h++) {
            float2 u = un0[h * 32 * 66 + c];
            unsigned long long u1 = pk2(u.x, u.x);
            unsigned long long u2 = pk2(u.y, u.y);
            fma2(acc[h][0], wv1.x, u1);
            fma2(acc[h][1], wv1.y, u1);
            fma2(acc[h][2], wv1b.x, u1);
            fma2(acc[h][3], wv1b.y, u1);
            fma2(acc[h][0], wv2.x, u2);
            fma2(acc[h][1], wv2.y, u2);
            fma2(acc[h][2], wv2b.x, u2);
            fma2(acc[h][3], wv2b.y, u2);
        }
    }

#pragma unroll
    for (int h = 0; h < 4; h++) {
        float r[8];
#pragma unroll
        for (int qq = 0; qq < 4; qq++) upk2(acc[h][qq], r[qq * 2], r[qq * 2 + 1]);
        size_t rowo = ((size_t)t * N + n0 + nl + h * 32) * C;
#pragma unroll
        for (int qq = 0; qq < 2; qq++) {
            *(float4*)(out + rowo + dg + qq * 4) =
                make_float4(r[qq * 4], r[qq * 4 + 1], r[qq * 4 + 2], r[qq * 4 + 3]);
        }
    }
}

// ============================================================
extern "C" void kernel_launch(void* const* d_in, const int* in_sizes, int n_in,
                              void* d_out, int out_size) {
    const float* x = (const float*)d_in[0];
    const int* adj = (const int*)d_in[1];
    const float* W = (const float*)d_in[2];
    const float* asrc = (const float*)d_in[3];
    const float* adst = (const float*)d_in[4];
    const float* bias = (const float*)d_in[5];
    const float* t1w = (const float*)d_in[6];
    const float* t2w = (const float*)d_in[7];
    float* out = (float*)d_out;

    cudaFuncSetAttribute(kA, cudaFuncAttributeMaxDynamicSharedMemorySize, KA_SMEM);
    cudaFuncSetAttribute(kB, cudaFuncAttributeMaxDynamicSharedMemorySize, KB_SMEM);
    cudaFuncSetAttribute(kC, cudaFuncAttributeMaxDynamicSharedMemorySize, KC_SMEM);

    kW<<<1, 256>>>(W);
    kA<<<dim3(N / 64, T), 128, KA_SMEM>>>(x, asrc, adst);
    kB<<<dim3(N / 128, T), 512, KB_SMEM>>>(adj, bias);
    kC<<<dim3(N / 128, T), 256, KC_SMEM>>>(t1w, t2w, out);
}

// round 17
// speedup vs baseline: 1.0565x; 1.0565x over previous
#include <cuda_runtime.h>
#include <cuda_fp16.h>
#include <math.h>
#include <stdint.h>

#define T 8
#define N 2048
#define F 128
#define C 64

// ---------------- device scratch ----------------
__device__ float g_es[T * N];
__device__ float g_ed[T * N];
__device__ float g_out[T * N * C];
__device__ __half g_hThi[T * C * N];   // h transposed fp16: [t][c][n]
__device__ __half g_Whi[C * F];        // W^T hi fp16: [c][k]
__device__ __half g_Wlo[C * F];        // W^T lo fp16

// ---------------- helpers ----------------
__device__ __forceinline__ uint32_t smem_u32(const void* p) {
    uint32_t a;
    asm("{ .reg .u64 t; cvta.to.shared.u64 t, %1; cvt.u32.u64 %0, t; }"
        : "=r"(a) : "l"(p));
    return a;
}
#define CP_ASYNC16(dst, src) \
    asm volatile("cp.async.cg.shared.global [%0], [%1], 16;" :: "r"(dst), "l"(src) : "memory")
#define CP_COMMIT() asm volatile("cp.async.commit_group;" ::: "memory")
#define CP_WAIT0() asm volatile("cp.async.wait_group 0;" ::: "memory")
#define CP_WAIT1() asm volatile("cp.async.wait_group 1;" ::: "memory")

__device__ __forceinline__ void ldsm4(uint32_t& r0, uint32_t& r1, uint32_t& r2,
                                      uint32_t& r3, uint32_t addr) {
    asm volatile("ldmatrix.sync.aligned.m8n8.x4.shared.b16 {%0,%1,%2,%3}, [%4];"
                 : "=r"(r0), "=r"(r1), "=r"(r2), "=r"(r3) : "r"(addr));
}
__device__ __forceinline__ void mma16816(float* d, const uint32_t* a, uint32_t b0,
                                         uint32_t b1) {
    asm volatile(
        "mma.sync.aligned.m16n8k16.row.col.f32.f16.f16.f32 "
        "{%0,%1,%2,%3}, {%4,%5,%6,%7}, {%8,%9}, {%0,%1,%2,%3};"
        : "+f"(d[0]), "+f"(d[1]), "+f"(d[2]), "+f"(d[3])
        : "r"(a[0]), "r"(a[1]), "r"(a[2]), "r"(a[3]), "r"(b0), "r"(b1));
}
__device__ __forceinline__ uint32_t pack_p(float p0, float p1) {
    __half2 h = __floats2half2_rn(p0, p1);
    return *(uint32_t*)&h;
}

// ---------------- f32x2 helpers ----------------
__device__ __forceinline__ unsigned long long pk2(float lo, float hi) {
    unsigned long long r;
    asm("mov.b64 %0, {%1, %2};" : "=l"(r) : "f"(lo), "f"(hi));
    return r;
}
__device__ __forceinline__ void upk2(unsigned long long v, float& lo, float& hi) {
    asm("mov.b64 {%0, %1}, %2;" : "=f"(lo), "=f"(hi) : "l"(v));
}
__device__ __forceinline__ void fma2(unsigned long long& d, unsigned long long a,
                                     unsigned long long b) {
    asm("fma.rn.f32x2 %0, %1, %2, %0;" : "+l"(d) : "l"(a), "l"(b));
}

// ============================================================
// Kernel W: one-time W -> transposed hi/lo fp16 (global)
// ============================================================
__global__ __launch_bounds__(256) void kW(const float* __restrict__ W) {
#pragma unroll
    for (int i = 0; i < 32; i++) {
        int e = threadIdx.x + i * 256;
        int k = e >> 6, c = e & 63;
        float v = W[e];
        __half h = __float2half_rn(v);
        g_Whi[c * F + k] = h;
        g_Wlo[c * F + k] = __float2half_rn(v - __half2float(h));
    }
}

// ============================================================
// Kernel A (HMMA): h = x @ W via split-fp16 (3 products).
// ============================================================
#define KA_WHI  0
#define KA_WLO  17408
#define KA_XHI  34816
#define KA_XLO  52224
#define KA_HHI  KA_XHI
#define KA_SMEM 69632

__global__ __launch_bounds__(128) void kA(const float* __restrict__ x,
                                          const float* __restrict__ asrc,
                                          const float* __restrict__ adst) {
    extern __shared__ __align__(16) char smA[];
    __half* xh = (__half*)(smA + KA_XHI);
    __half* xl = (__half*)(smA + KA_XLO);
    uint32_t smb = smem_u32(smA);

    int tid = threadIdx.x;
    int lane = tid & 31;
    int w = tid >> 5;
    int t = blockIdx.y;
    int n0 = blockIdx.x * 64;

#pragma unroll
    for (int r = 0; r < 8; r++) {
        int u = tid + r * 128;
        int c = u >> 4, seg = u & 15;
        uint32_t doff = (uint32_t)(c * 136 + seg * 8) * 2;
        CP_ASYNC16(smb + KA_WHI + doff, g_Whi + c * F + seg * 8);
        CP_ASYNC16(smb + KA_WLO + doff, g_Wlo + c * F + seg * 8);
    }
    CP_COMMIT();

    {
        int row = tid >> 1, half = tid & 1;
        const float4* xr4 =
            (const float4*)(x + ((size_t)t * N + n0 + row) * F + half * 64);
        __half* xhp = xh + row * 136 + half * 64;
        __half* xlp = xl + row * 136 + half * 64;
#pragma unroll
        for (int j = 0; j < 16; j++) {
            float4 v = xr4[j];
            __half2 h01 = __floats2half2_rn(v.x, v.y);
            __half2 h23 = __floats2half2_rn(v.z, v.w);
            float2 f01 = __half22float2(h01);
            float2 f23 = __half22float2(h23);
            __half2 l01 = __floats2half2_rn(v.x - f01.x, v.y - f01.y);
            __half2 l23 = __floats2half2_rn(v.z - f23.x, v.w - f23.y);
            *(uint32_t*)(xhp + j * 4) = *(uint32_t*)&h01;
            *(uint32_t*)(xhp + j * 4 + 2) = *(uint32_t*)&h23;
            *(uint32_t*)(xlp + j * 4) = *(uint32_t*)&l01;
            *(uint32_t*)(xlp + j * 4 + 2) = *(uint32_t*)&l23;
        }
    }
    CP_WAIT0();
    __syncthreads();

    float d[8][4];
#pragma unroll
    for (int nt = 0; nt < 8; nt++)
#pragma unroll
        for (int q = 0; q < 4; q++) d[nt][q] = 0.f;

    uint32_t xhi_b = smb + KA_XHI;
    uint32_t xlo_b = smb + KA_XLO;
    uint32_t whi_b = smb + KA_WHI;
    uint32_t wlo_b = smb + KA_WLO;
    int r0 = w * 16;
    uint32_t rowOffA = (lane & 7) + ((lane >> 3) & 1) * 8;
    uint32_t colOffA = (lane >> 4) * 8;
    uint32_t rowB = ((lane >> 4) << 3) + (lane & 7);
    uint32_t colB = ((lane >> 3) & 1) * 8;

#pragma unroll
    for (int ks = 0; ks < 8; ks++) {
        uint32_t kb = ks * 16;
        uint32_t aoff = ((r0 + rowOffA) * 136 + kb + colOffA) * 2;
        uint32_t ahi[4], alo[4];
        ldsm4(ahi[0], ahi[1], ahi[2], ahi[3], xhi_b + aoff);
        ldsm4(alo[0], alo[1], alo[2], alo[3], xlo_b + aoff);
#pragma unroll
        for (int cg = 0; cg < 4; cg++) {
            uint32_t boff = ((cg * 16 + rowB) * 136 + kb + colB) * 2;
            uint32_t h0, h1, h2, h3, l0, l1, l2, l3;
            ldsm4(h0, h1, h2, h3, whi_b + boff);
            ldsm4(l0, l1, l2, l3, wlo_b + boff);
            mma16816(d[cg * 2], ahi, h0, h1);
            mma16816(d[cg * 2], ahi, l0, l1);
            mma16816(d[cg * 2], alo, h0, h1);
            mma16816(d[cg * 2 + 1], ahi, h2, h3);
            mma16816(d[cg * 2 + 1], ahi, l2, l3);
            mma16816(d[cg * 2 + 1], alo, h2, h3);
        }
    }

    int r1 = r0 + (lane >> 2), r2 = r1 + 8;
    float es1 = 0.f, ed1 = 0.f, es2 = 0.f, ed2 = 0.f;
#pragma unroll
    for (int nt = 0; nt < 8; nt++) {
        int c = nt * 8 + 2 * (lane & 3);
        float a0 = asrc[c], a1 = asrc[c + 1];
        float b0 = adst[c], b1 = adst[c + 1];
        es1 += d[nt][0] * a0 + d[nt][1] * a1;
        ed1 += d[nt][0] * b0 + d[nt][1] * b1;
        es2 += d[nt][2] * a0 + d[nt][3] * a1;
        ed2 += d[nt][2] * b0 + d[nt][3] * b1;
    }
#pragma unroll
    for (int off = 1; off < 4; off <<= 1) {
        es1 += __shfl_xor_sync(0xffffffffu, es1, off);
        ed1 += __shfl_xor_sync(0xffffffffu, ed1, off);
        es2 += __shfl_xor_sync(0xffffffffu, es2, off);
        ed2 += __shfl_xor_sync(0xffffffffu, ed2, off);
    }
    if ((lane & 3) == 0) {
        g_es[t * N + n0 + r1] = es1;
        g_ed[t * N + n0 + r1] = ed1;
        g_es[t * N + n0 + r2] = es2;
        g_ed[t * N + n0 + r2] = ed2;
    }

    __syncthreads();
    __half* hh = (__half*)(smA + KA_HHI);
#pragma unroll
    for (int nt = 0; nt < 8; nt++) {
        int c = nt * 8 + 2 * (lane & 3);
        hh[c * 136 + r1] = __float2half_rn(d[nt][0]);
        hh[(c + 1) * 136 + r1] = __float2half_rn(d[nt][1]);
        hh[c * 136 + r2] = __float2half_rn(d[nt][2]);
        hh[(c + 1) * 136 + r2] = __float2half_rn(d[nt][3]);
    }
    __syncthreads();

    __half* dhi = g_hThi + (size_t)t * C * N;
#pragma unroll
    for (int i = 0; i < 4; i++) {
        int u = tid + i * 128;
        int c = u >> 3, seg = u & 7;
        *(uint4*)(dhi + (size_t)c * N + n0 + seg * 8) = *(uint4*)(hh + c * 136 + seg * 8);
    }
}

// ============================================================
// Kernel B: masked-softmax aggregation via fp16 HMMA.
// 512 threads, kt-split warp pairs; 3-deep cp.async buffers,
// ONE sync/chunk; fused mask+P build; self-loop post-correction
// applied POST-reduce (counted exactly once).
// ============================================================
#define ADJ_STRIDE 132
#define ADJ_BYTES  33792
#define BB_OFF   0                     // 16384
#define HS_OFF   16384                 // 3 x 9216 = 27648
#define ADJ_OFF  44032                 // 3 x 33792 = 101376
#define RED_OFF  145408                // 2048
#define BIAS_OFF 147456                // 256
#define KB_SMEM  147712
#define DCOMB_OFF ADJ_OFF

__global__ __launch_bounds__(512) void kB(const int* __restrict__ adj,
                                          const float* __restrict__ bias) {
    extern __shared__ __align__(16) char sm[];
    float2* BB = (float2*)(sm + BB_OFF);
    float* red = (float*)(sm + RED_OFF);
    float* bias_s = (float*)(sm + BIAS_OFF);
    uint32_t smb = smem_u32(sm);

    int tid = threadIdx.x;
    int wid = tid >> 5;
    int lane = tid & 31;
    int wl = wid & 7;
    int kh = wid >> 3;
    int t = blockIdx.y;
    int i0 = blockIdx.x * 128;

    const int* abase = adj + (size_t)t * N * N + i0;
    const __half* hhib = g_hThi + (size_t)t * C * N;

    // ---- prologue: chunks 0 and 1 into bufs 0,1 ----
#pragma unroll
    for (int b = 0; b < 2; b++) {
#pragma unroll
        for (int r = 0; r < 4; r++) {
            int u = tid + r * 512;
            int j = u >> 5, off = u & 31;
            CP_ASYNC16(smb + ADJ_OFF + b * ADJ_BYTES + j * 528 + off * 16,
                       abase + (size_t)(b * 64 + j) * N + off * 4);
        }
        int c = tid >> 3, o = tid & 7;
        uint32_t doff = (uint32_t)(c * 72 + o * 8) * 2;
        CP_ASYNC16(smb + HS_OFF + b * 9216 + doff, hhib + (size_t)c * N + b * 64 + o * 8);
        CP_COMMIT();
    }

    if (tid < 16) ((float4*)bias_s)[tid] = ((const float4*)bias)[tid];

    // ---- e_s staging + max + transform ----
    float lmax = -1e30f;
#pragma unroll
    for (int r = 0; r < 4; r++) {
        float v = g_es[t * N + tid + r * 512];
        BB[tid + r * 512].x = v;
        lmax = fmaxf(lmax, v);
    }
    red[tid] = lmax;
    __syncthreads();
    for (int s = 256; s > 0; s >>= 1) {
        if (tid < s) red[tid] = fmaxf(red[tid], red[tid + s]);
        __syncthreads();
    }
    float esmax = red[0];
#pragma unroll
    for (int r = 0; r < 4; r++) {
        int j = tid + r * 512;
        float v = BB[j].x;
        BB[j] = make_float2(__expf(v - esmax), __expf(0.2f * (v - esmax)));
    }

    // ---- per-row constants ----
    int q = lane & 3;
    int c0j = 2 * q;
    int qd = lane >> 2;
    int il1 = wl * 16 + qd;
    int il2 = il1 + 8;
    int gi1 = i0 + il1, gi2 = i0 + il2;
    float ed1 = g_ed[t * N + gi1], ed2 = g_ed[t * N + gi2];
    float xm1 = ed1 + esmax, xm2 = ed2 + esmax;
    float M1 = fmaxf(xm1, 0.2f * xm1), M2 = fmaxf(xm2, 0.2f * xm2);
    float Ai1 = __expf(xm1 - M1), A2i1 = __expf(0.2f * xm1 - M1);
    float Ai2 = __expf(xm2 - M2), A2i2 = __expf(0.2f * xm2 - M2);

    // diag entries for self-loop post-correction (read once)
    int diag1 = abase[(size_t)gi1 * N + il1];
    int diag2 = abase[(size_t)gi2 * N + il2];

    float d[8][4];
#pragma unroll
    for (int nt = 0; nt < 8; nt++)
#pragma unroll
        for (int qq = 0; qq < 4; qq++) d[nt][qq] = 0.f;
    float sum1 = 0.f, sum2 = 0.f;

    uint32_t rowa = ((lane >> 4) << 3) + (lane & 7);
    uint32_t cola = ((lane >> 3) & 1) * 8;

    __syncthreads();   // BB ready

#pragma unroll 1
    for (int k = 0; k < 32; k++) {
        int j0 = k * 64;
        int bufk = k % 3;
        if (k < 31) { CP_WAIT1(); } else { CP_WAIT0(); }
        __syncthreads();   // chunk-k data visible; all prior compute done

        // ---- refill buf (k+2)%3 with chunk k+2 (never the current buf) ----
        if (k + 2 < 32) {
            int bufn = (k + 2) % 3;
            int jn = j0 + 128;
#pragma unroll
            for (int r = 0; r < 4; r++) {
                int u = tid + r * 512;
                int j = u >> 5, off = u & 31;
                CP_ASYNC16(smb + ADJ_OFF + bufn * ADJ_BYTES + j * 528 + off * 16,
                           abase + (size_t)(jn + j) * N + off * 4);
            }
            int c = tid >> 3, o = tid & 7;
            uint32_t doff = (uint32_t)(c * 72 + o * 8) * 2;
            CP_ASYNC16(smb + HS_OFF + (uint32_t)bufn * 9216 + doff,
                       hhib + (size_t)c * N + jn + o * 8);
            CP_COMMIT();
        }

        const int* adjraw = (const int*)(sm + ADJ_OFF + bufk * ADJ_BYTES);
        uint32_t hhi_u = smb + HS_OFF + (uint32_t)bufk * 9216;

#pragma unroll
        for (int ktl = 0; ktl < 2; ktl++) {
            int kt = kh * 2 + ktl;
            int jl = kt * 16 + c0j;

            float p1[4], p2[4];
#pragma unroll
            for (int dIdx = 0; dIdx < 4; dIdx++) {
                int dlt = (dIdx & 1) + (dIdx >> 1) * 8;
                int jj = jl + dlt;
                float2 bb = BB[j0 + jj];
                int v1 = adjraw[jj * ADJ_STRIDE + il1];
                int v2 = adjraw[jj * ADJ_STRIDE + il2];
                float pc1 = fmaxf(Ai1 * bb.x, A2i1 * bb.y);
                float pc2 = fmaxf(Ai2 * bb.x, A2i2 * bb.y);
                p1[dIdx] = (v1 != 0) ? pc1 : 0.f;
                p2[dIdx] = (v2 != 0) ? pc2 : 0.f;
            }
            sum1 += (p1[0] + p1[1]) + (p1[2] + p1[3]);
            sum2 += (p2[0] + p2[1]) + (p2[2] + p2[3]);

            uint32_t ap[4];
            ap[0] = pack_p(p1[0], p1[1]);
            ap[1] = pack_p(p2[0], p2[1]);
            ap[2] = pack_p(p1[2], p1[3]);
            ap[3] = pack_p(p2[2], p2[3]);

            uint32_t lcol = (uint32_t)(kt * 16) + cola;
#pragma unroll
            for (int cg = 0; cg < 4; cg++) {
                uint32_t roff = ((uint32_t)(cg * 16) + rowa) * 144 + lcol * 2;
                uint32_t h0, h1, h2, h3;
                ldsm4(h0, h1, h2, h3, hhi_u + roff);
                mma16816(d[cg * 2], ap, h0, h1);
                mma16816(d[cg * 2 + 1], ap, h2, h3);
            }
        }
    }

    // ---- self-loop terms (per-thread, NOT added to pre-reduce sums) ----
    float ps1 = (diag1 == 0) ? fmaxf(Ai1 * BB[gi1].x, A2i1 * BB[gi1].y) : 0.f;
    float ps2 = (diag2 == 0) ? fmaxf(Ai2 * BB[gi2].x, A2i2 * BB[gi2].y) : 0.f;

    // numerator correction: kh==0 threads own the final d; each (nt,q)
    // covers distinct columns so this counts once per column.
    if (kh == 0 && (ps1 != 0.f || ps2 != 0.f)) {
#pragma unroll
        for (int nt = 0; nt < 8; nt++) {
            int c = nt * 8 + c0j;
            d[nt][0] += ps1 * __half2float(hhib[(size_t)c * N + gi1]);
            d[nt][1] += ps1 * __half2float(hhib[(size_t)(c + 1) * N + gi1]);
            d[nt][2] += ps2 * __half2float(hhib[(size_t)c * N + gi2]);
            d[nt][3] += ps2 * __half2float(hhib[(size_t)(c + 1) * N + gi2]);
        }
    }

    // ---- combine kt-halves ----
    sum1 += __shfl_xor_sync(0xffffffffu, sum1, 1);
    sum1 += __shfl_xor_sync(0xffffffffu, sum1, 2);
    sum2 += __shfl_xor_sync(0xffffffffu, sum2, 1);
    sum2 += __shfl_xor_sync(0xffffffffu, sum2, 2);

    __syncthreads();
    float* dc = (float*)(sm + DCOMB_OFF);
    float* sums_hi = (float*)(sm + RED_OFF);

    if (kh == 1) {
#pragma unroll
        for (int nt = 0; nt < 8; nt++)
            *(float4*)(dc + wl * 1024 + nt * 128 + lane * 4) =
                make_float4(d[nt][0], d[nt][1], d[nt][2], d[nt][3]);
        if ((lane & 3) == 0) {
            sums_hi[il1] = sum1;
            sums_hi[il2] = sum2;
        }
    }
    __syncthreads();

    if (kh == 0) {
        // add self term exactly once, post-reduce
        float st1 = sum1 + sums_hi[il1] + ps1;
        float st2 = sum2 + sums_hi[il2] + ps2;
        float s1 = 1.f / st1, s2 = 1.f / st2;

        float* o1 = g_out + ((size_t)t * N + gi1) * C;
        float* o2 = g_out + ((size_t)t * N + gi2) * C;
        int q2o = 2 * q;
#pragma unroll
        for (int nt = 0; nt < 8; nt++) {
            float4 pd = *(const float4*)(dc + wl * 1024 + nt * 128 + lane * 4);
            int c = nt * 8 + q2o;
            *(float2*)(o1 + c) = make_float2((d[nt][0] + pd.x) * s1 + bias_s[c],
                                             (d[nt][1] + pd.y) * s1 + bias_s[c + 1]);
            *(float2*)(o2 + c) = make_float2((d[nt][2] + pd.z) * s2 + bias_s[c],
                                             (d[nt][3] + pd.w) * s2 + bias_s[c + 1]);
        }
    }
}

// ============================================================
// Kernel C: inline cosine sims + temporal matvecs.
// 128 nodes/CTA, 4 nodes per thread.
// ============================================================
#define KC_W1 0
#define KC_W2 16384
#define KC_US 32768        // 128 x 66 float2 = 67584
#define KC_SMEM 100352

__global__ __launch_bounds__(256) void kC(const float* __restrict__ t1w,
                                          const float* __restrict__ t2w,
                                          float* __restrict__ out) {
    extern __shared__ __align__(16) char smC[];
    float* w1 = (float*)(smC + KC_W1);
    float* w2 = (float*)(smC + KC_W2);
    float2* us = (float2*)(smC + KC_US);

    int tid = threadIdx.x;
    int t = blockIdx.y;
    int n0 = blockIdx.x * 128;

#pragma unroll
    for (int r = 0; r < 4; r++) {
        ((float4*)w1)[tid + r * 256] = ((const float4*)t1w)[tid + r * 256];
        ((float4*)w2)[tid + r * 256] = ((const float4*)t2w)[tid + r * 256];
    }

    int nl = tid >> 3;
    int dg = (tid & 7) * 8;

    float curH[4][8];
    unsigned long long acc[4][4];

#pragma unroll
    for (int half = 0; half < 4; half++) {
        int node = nl + half * 32;
        size_t rowo = ((size_t)t * N + n0 + node) * C;
        float cur[8], prv[8], nxt[8];
#pragma unroll
        for (int qq = 0; qq < 2; qq++) {
            float4 v = *(const float4*)(g_out + rowo + dg + qq * 4);
            cur[qq * 4] = v.x; cur[qq * 4 + 1] = v.y;
            cur[qq * 4 + 2] = v.z; cur[qq * 4 + 3] = v.w;
        }
        if (t >= 1) {
#pragma unroll
            for (int qq = 0; qq < 2; qq++) {
                float4 v = *(const float4*)(g_out + rowo - (size_t)N * C + dg + qq * 4);
                prv[qq * 4] = v.x; prv[qq * 4 + 1] = v.y;
                prv[qq * 4 + 2] = v.z; prv[qq * 4 + 3] = v.w;
            }
        } else {
#pragma unroll
            for (int dd = 0; dd < 8; dd++) prv[dd] = 0.f;
        }
        if (t < T - 1) {
#pragma unroll
            for (int qq = 0; qq < 2; qq++) {
                float4 v = *(const float4*)(g_out + rowo + (size_t)N * C + dg + qq * 4);
                nxt[qq * 4] = v.x; nxt[qq * 4 + 1] = v.y;
                nxt[qq * 4 + 2] = v.z; nxt[qq * 4 + 3] = v.w;
            }
        } else {
#pragma unroll
            for (int dd = 0; dd < 8; dd++) nxt[dd] = 0.f;
        }

        float ab = 0.f, bc = 0.f, na = 0.f, nb = 0.f, nc = 0.f;
#pragma unroll
        for (int dd = 0; dd < 8; dd++) {
            ab = fmaf(prv[dd], cur[dd], ab);
            bc = fmaf(cur[dd], nxt[dd], bc);
            na = fmaf(prv[dd], prv[dd], na);
            nb = fmaf(cur[dd], cur[dd], nb);
            nc = fmaf(nxt[dd], nxt[dd], nc);
        }
#pragma unroll
        for (int off = 1; off < 8; off <<= 1) {
            ab += __shfl_xor_sync(0xffffffffu, ab, off);
            bc += __shfl_xor_sync(0xffffffffu, bc, off);
            na += __shfl_xor_sync(0xffffffffu, na, off);
            nb += __shfl_xor_sync(0xffffffffu, nb, off);
            nc += __shfl_xor_sync(0xffffffffu, nc, off);
        }
        float rb = fmaxf(sqrtf(nb), 1e-8f);
        float tem_prev = ab / (fmaxf(sqrtf(na), 1e-8f) * rb);
        float tem_next = bc / (rb * fmaxf(sqrtf(nc), 1e-8f));

        float2* urow = us + node * 66 + dg;
#pragma unroll
        for (int dd = 0; dd < 8; dd++)
            urow[dd] = make_float2(tem_next * nxt[dd], tem_prev * prv[dd]);

#pragma unroll
        for (int dd = 0; dd < 8; dd++) curH[half][dd] = cur[dd];
    }
    __syncthreads();

#pragma unroll
    for (int h = 0; h < 4; h++)
#pragma unroll
        for (int qq = 0; qq < 4; qq++)
            acc[h][qq] = pk2(curH[h][qq * 2], curH[h][qq * 2 + 1]);

    const float2* un0 = us + nl * 66;
#pragma unroll 2
    for (int c = 0; c < C; c++) {
        const ulonglong2* r1 = (const ulonglong2*)(w1 + c * C + dg);
        const ulonglong2* r2 = (const ulonglong2*)(w2 + c * C + dg);
        ulonglong2 wv1 = r1[0], wv1b = r1[1];
        ulonglong2 wv2 = r2[0], wv2b = r2[1];
#pragma unroll
        for (int h = 0; h < 4; h++) {
            float2 u = un0[h * 32 * 66 + c];
            unsigned long long u1 = pk2(u.x, u.x);
            unsigned long long u2 = pk2(u.y, u.y);
            fma2(acc[h][0], wv1.x, u1);
            fma2(acc[h][1], wv1.y, u1);
            fma2(acc[h][2], wv1b.x, u1);
            fma2(acc[h][3], wv1b.y, u1);
            fma2(acc[h][0], wv2.x, u2);
            fma2(acc[h][1], wv2.y, u2);
            fma2(acc[h][2], wv2b.x, u2);
            fma2(acc[h][3], wv2b.y, u2);
        }
    }

#pragma unroll
    for (int h = 0; h < 4; h++) {
        float r[8];
#pragma unroll
        for (int qq = 0; qq < 4; qq++) upk2(acc[h][qq], r[qq * 2], r[qq * 2 + 1]);
        size_t rowo = ((size_t)t * N + n0 + nl + h * 32) * C;
#pragma unroll
        for (int qq = 0; qq < 2; qq++) {
            *(float4*)(out + rowo + dg + qq * 4) =
                make_float4(r[qq * 4], r[qq * 4 + 1], r[qq * 4 + 2], r[qq * 4 + 3]);
        }
    }
}

// ============================================================
extern "C" void kernel_launch(void* const* d_in, const int* in_sizes, int n_in,
                              void* d_out, int out_size) {
    const float* x = (const float*)d_in[0];
    const int* adj = (const int*)d_in[1];
    const float* W = (const float*)d_in[2];
    const float* asrc = (const float*)d_in[3];
    const float* adst = (const float*)d_in[4];
    const float* bias = (const float*)d_in[5];
    const float* t1w = (const float*)d_in[6];
    const float* t2w = (const float*)d_in[7];
    float* out = (float*)d_out;

    cudaFuncSetAttribute(kA, cudaFuncAttributeMaxDynamicSharedMemorySize, KA_SMEM);
    cudaFuncSetAttribute(kB, cudaFuncAttributeMaxDynamicSharedMemorySize, KB_SMEM);
    cudaFuncSetAttribute(kC, cudaFuncAttributeMaxDynamicSharedMemorySize, KC_SMEM);

    kW<<<1, 256>>>(W);
    kA<<<dim3(N / 64, T), 128, KA_SMEM>>>(x, asrc, adst);
    kB<<<dim3(N / 128, T), 512, KB_SMEM>>>(adj, bias);
    kC<<<dim3(N / 128, T), 256, KC_SMEM>>>(t1w, t2w, out);
}